// round 1
// baseline (speedup 1.0000x reference)
#include <cuda_runtime.h>

#define Bc   2
#define Mq   16384
#define Np   4096
#define Cin  128
#define CsF  256
#define DoC  128
#define K1   384
#define NCOLS (Bc*Mq)        // 32768
#define NBLK  256            // gemm1/gemm2 grid size (32768/128)

// ---------------- scratch (device globals; no runtime allocation) -------------
__device__ float d_W1t[K1*DoC];          // W1 transposed, k-major [k][o]
__device__ float d_W2t[DoC*DoC];         // W2 transposed, k-major [k][o]
__device__ float d_P  [Bc*Np*DoC];       // P[b][n][o] = (W1[:,128:] @ sub_x)^T
__device__ int   d_idx[Bc*Mq*3];
__device__ float d_w  [Bc*Mq*3];
__device__ float d_z1 [Bc*DoC*Mq];
__device__ float d_z2 [Bc*DoC*Mq];
__device__ float d_psum[NBLK*DoC];
__device__ float d_psq [NBLK*DoC];
__device__ float d_bn1[2*DoC];           // [a (=g*rstd)], [d (=b-mean*a)]
__device__ float d_bn2[2*DoC];

// ---------------- W transpose ----------------
__global__ __launch_bounds__(256) void transpose_w_kernel(
    const float* __restrict__ W1, const float* __restrict__ W2) {
  int e = blockIdx.x * 256 + threadIdx.x;
  if (e < K1*DoC) {
    int k = e >> 7, o = e & 127;
    d_W1t[e] = W1[o*K1 + k];
  } else {
    int e2 = e - K1*DoC;           // < 16384
    int k = e2 >> 7, o = e2 & 127;
    d_W2t[e2] = W2[o*DoC + k];
  }
}

// ---------------- 3-NN search ----------------
__global__ __launch_bounds__(256) void knn_kernel(
    const float* __restrict__ xyz, const float* __restrict__ sub_xyz) {
  __shared__ float px[Np], py[Np], pz[Np];   // 48KB
  int b = blockIdx.x >> 6;                    // 64 blocks per batch
  int m = ((blockIdx.x & 63) << 8) + threadIdx.x;
  const float* sp = sub_xyz + (size_t)b * 3 * Np;
  for (int i = threadIdx.x; i < Np; i += 256) {
    px[i] = sp[i];
    py[i] = sp[Np + i];
    pz[i] = sp[2*Np + i];
  }
  __syncthreads();
  const float* qp = xyz + (size_t)b * 3 * Mq;
  float qx = qp[m], qy = qp[Mq + m], qz = qp[2*Mq + m];

  float c0 = 3.4e38f, c1 = 3.4e38f, c2 = 3.4e38f;
  int j0 = 0, j1 = 0, j2 = 0;
  #pragma unroll 4
  for (int i = 0; i < Np; i++) {
    float dx = qx - px[i];
    float dy = qy - py[i];
    float dz = qz - pz[i];
    float d2 = fmaf(dx, dx, fmaf(dy, dy, dz * dz));
    if (d2 < c2) {
      if (d2 < c1) {
        c2 = c1; j2 = j1;
        if (d2 < c0) { c1 = c0; j1 = j0; c0 = d2; j0 = i; }
        else         { c1 = d2; j1 = i; }
      } else { c2 = d2; j2 = i; }
    }
  }
  float w0 = 1.0f / (c0 + 1e-8f);
  float w1 = 1.0f / (c1 + 1e-8f);
  float w2 = 1.0f / (c2 + 1e-8f);
  float inv = 1.0f / (w0 + w1 + w2);
  size_t base = ((size_t)b * Mq + m) * 3;
  d_idx[base + 0] = j0; d_idx[base + 1] = j1; d_idx[base + 2] = j2;
  d_w[base + 0] = w0 * inv; d_w[base + 1] = w1 * inv; d_w[base + 2] = w2 * inv;
}

// ---------------- P = W1[:,128:384] @ sub_x, stored [b][n][o] ----------------
__global__ __launch_bounds__(256) void gemmP_kernel(const float* __restrict__ sub_x) {
  __shared__ float Ws[32][128];
  __shared__ float Xs[32][128];
  int b  = blockIdx.x >> 5;
  int n0 = (blockIdx.x & 31) << 7;
  int tid = threadIdx.x;
  int tx = tid & 15, ty = tid >> 4;
  const float* xb = sub_x + (size_t)b * CsF * Np;
  float acc[8][8];
  #pragma unroll
  for (int i = 0; i < 8; i++)
    #pragma unroll
    for (int j = 0; j < 8; j++) acc[i][j] = 0.0f;

  for (int kc = 0; kc < CsF; kc += 32) {
    for (int e = tid; e < 4096; e += 256) {
      int kk = e >> 7, c = e & 127;
      Ws[kk][c] = d_W1t[(size_t)(Cin + kc + kk) * DoC + c];
      Xs[kk][c] = xb[(size_t)(kc + kk) * Np + n0 + c];
    }
    __syncthreads();
    #pragma unroll
    for (int kk = 0; kk < 32; kk++) {
      float a[8], bb[8];
      *(float4*)&a[0]  = *(const float4*)&Ws[kk][ty*8];
      *(float4*)&a[4]  = *(const float4*)&Ws[kk][ty*8+4];
      *(float4*)&bb[0] = *(const float4*)&Xs[kk][tx*8];
      *(float4*)&bb[4] = *(const float4*)&Xs[kk][tx*8+4];
      #pragma unroll
      for (int i = 0; i < 8; i++)
        #pragma unroll
        for (int j = 0; j < 8; j++) acc[i][j] = fmaf(a[i], bb[j], acc[i][j]);
    }
    __syncthreads();
  }
  #pragma unroll
  for (int j = 0; j < 8; j++) {
    float* dst = &d_P[(((size_t)b * Np) + n0 + tx*8 + j) * DoC + ty*8];
    float4 v0 = make_float4(acc[0][j], acc[1][j], acc[2][j], acc[3][j]);
    float4 v1 = make_float4(acc[4][j], acc[5][j], acc[6][j], acc[7][j]);
    *(float4*)dst = v0; *(float4*)(dst + 4) = v1;
  }
}

// ---------------- z1 = W1a @ x + gather(P), + block stats ----------------
__global__ __launch_bounds__(256) void gemm1_kernel(const float* __restrict__ x) {
  __shared__ float Ws[32][128];
  __shared__ float Xs[32][128];
  __shared__ int   sidx[384];
  __shared__ float sw[384];
  __shared__ float red[16][8][17];
  int n0g = blockIdx.x << 7;
  int b   = n0g >> 14;
  int m0  = n0g & (Mq - 1);
  int tid = threadIdx.x;
  int tx = tid & 15, ty = tid >> 4;
  const float* xb = x + (size_t)b * Cin * Mq;
  float acc[8][8];
  #pragma unroll
  for (int i = 0; i < 8; i++)
    #pragma unroll
    for (int j = 0; j < 8; j++) acc[i][j] = 0.0f;

  for (int kc = 0; kc < Cin; kc += 32) {
    for (int e = tid; e < 4096; e += 256) {
      int kk = e >> 7, c = e & 127;
      Ws[kk][c] = d_W1t[(size_t)(kc + kk) * DoC + c];
      Xs[kk][c] = xb[(size_t)(kc + kk) * Mq + m0 + c];
    }
    __syncthreads();
    #pragma unroll
    for (int kk = 0; kk < 32; kk++) {
      float a[8], bb[8];
      *(float4*)&a[0]  = *(const float4*)&Ws[kk][ty*8];
      *(float4*)&a[4]  = *(const float4*)&Ws[kk][ty*8+4];
      *(float4*)&bb[0] = *(const float4*)&Xs[kk][tx*8];
      *(float4*)&bb[4] = *(const float4*)&Xs[kk][tx*8+4];
      #pragma unroll
      for (int i = 0; i < 8; i++)
        #pragma unroll
        for (int j = 0; j < 8; j++) acc[i][j] = fmaf(a[i], bb[j], acc[i][j]);
    }
    __syncthreads();
  }

  // gather-interpolate through P
  {
    size_t cb = ((size_t)b * Mq + m0) * 3;
    for (int e = tid; e < 384; e += 256) { sidx[e] = d_idx[cb + e]; sw[e] = d_w[cb + e]; }
  }
  __syncthreads();
  #pragma unroll
  for (int j = 0; j < 8; j++) {
    int col = tx*8 + j;
    #pragma unroll
    for (int t = 0; t < 3; t++) {
      int   id = sidx[col*3 + t];
      float wt = sw  [col*3 + t];
      const float* pr = &d_P[(((size_t)b * Np) + id) * DoC + ty*8];
      float4 p0 = *(const float4*)pr;
      float4 p1 = *(const float4*)(pr + 4);
      acc[0][j] = fmaf(wt, p0.x, acc[0][j]);
      acc[1][j] = fmaf(wt, p0.y, acc[1][j]);
      acc[2][j] = fmaf(wt, p0.z, acc[2][j]);
      acc[3][j] = fmaf(wt, p0.w, acc[3][j]);
      acc[4][j] = fmaf(wt, p1.x, acc[4][j]);
      acc[5][j] = fmaf(wt, p1.y, acc[5][j]);
      acc[6][j] = fmaf(wt, p1.z, acc[6][j]);
      acc[7][j] = fmaf(wt, p1.w, acc[7][j]);
    }
  }

  // store z1
  #pragma unroll
  for (int i = 0; i < 8; i++) {
    float* dst = &d_z1[((size_t)(b * DoC + ty*8 + i)) * Mq + m0 + tx*8];
    *(float4*)dst       = make_float4(acc[i][0], acc[i][1], acc[i][2], acc[i][3]);
    *(float4*)(dst + 4) = make_float4(acc[i][4], acc[i][5], acc[i][6], acc[i][7]);
  }

  // deterministic per-block channel stats
  #pragma unroll
  for (int i = 0; i < 8; i++) {
    float s = 0.0f;
    #pragma unroll
    for (int j = 0; j < 8; j++) s += acc[i][j];
    red[ty][i][tx] = s;
  }
  __syncthreads();
  if (tid < 128) {
    float s = 0.0f;
    #pragma unroll
    for (int t = 0; t < 16; t++) s += red[tid >> 3][tid & 7][t];
    d_psum[blockIdx.x * DoC + tid] = s;
  }
  __syncthreads();
  #pragma unroll
  for (int i = 0; i < 8; i++) {
    float s = 0.0f;
    #pragma unroll
    for (int j = 0; j < 8; j++) s += acc[i][j] * acc[i][j];
    red[ty][i][tx] = s;
  }
  __syncthreads();
  if (tid < 128) {
    float s = 0.0f;
    #pragma unroll
    for (int t = 0; t < 16; t++) s += red[tid >> 3][tid & 7][t];
    d_psq[blockIdx.x * DoC + tid] = s;
  }
}

// ---------------- BN finalize (per-channel affine a,d) ----------------
__global__ void bn_finalize_kernel(const float* __restrict__ g,
                                   const float* __restrict__ bias, int which) {
  int ch = threadIdx.x;  // 128 threads
  float s = 0.0f, q = 0.0f;
  for (int blk = 0; blk < NBLK; blk++) {
    s += d_psum[blk * DoC + ch];
    q += d_psq [blk * DoC + ch];
  }
  const float invN = 1.0f / (float)NCOLS;
  float mean = s * invN;
  float var  = q * invN - mean * mean;
  float rstd = rsqrtf(var + 1e-5f);
  float a = g[ch] * rstd;
  float d = bias[ch] - mean * a;
  float* ab = which ? d_bn2 : d_bn1;
  ab[ch] = a; ab[DoC + ch] = d;
}

// ---------------- z2 = W2 @ relu(bn1(z1)), + block stats ----------------
__global__ __launch_bounds__(256) void gemm2_kernel() {
  __shared__ float Ws[32][128];
  __shared__ float Xs[32][128];
  __shared__ float sa[128], sd[128];
  __shared__ float red[16][8][17];
  int n0g = blockIdx.x << 7;
  int b   = n0g >> 14;
  int m0  = n0g & (Mq - 1);
  int tid = threadIdx.x;
  int tx = tid & 15, ty = tid >> 4;
  if (tid < 128) { sa[tid] = d_bn1[tid]; sd[tid] = d_bn1[128 + tid]; }
  __syncthreads();

  float acc[8][8];
  #pragma unroll
  for (int i = 0; i < 8; i++)
    #pragma unroll
    for (int j = 0; j < 8; j++) acc[i][j] = 0.0f;

  for (int kc = 0; kc < DoC; kc += 32) {
    for (int e = tid; e < 4096; e += 256) {
      int kk = e >> 7, c = e & 127;
      int k  = kc + kk;
      Ws[kk][c] = d_W2t[(size_t)k * DoC + c];
      float v = d_z1[((size_t)(b * DoC + k)) * Mq + m0 + c];
      Xs[kk][c] = fmaxf(fmaf(sa[k], v, sd[k]), 0.0f);
    }
    __syncthreads();
    #pragma unroll
    for (int kk = 0; kk < 32; kk++) {
      float a[8], bb[8];
      *(float4*)&a[0]  = *(const float4*)&Ws[kk][ty*8];
      *(float4*)&a[4]  = *(const float4*)&Ws[kk][ty*8+4];
      *(float4*)&bb[0] = *(const float4*)&Xs[kk][tx*8];
      *(float4*)&bb[4] = *(const float4*)&Xs[kk][tx*8+4];
      #pragma unroll
      for (int i = 0; i < 8; i++)
        #pragma unroll
        for (int j = 0; j < 8; j++) acc[i][j] = fmaf(a[i], bb[j], acc[i][j]);
    }
    __syncthreads();
  }

  #pragma unroll
  for (int i = 0; i < 8; i++) {
    float* dst = &d_z2[((size_t)(b * DoC + ty*8 + i)) * Mq + m0 + tx*8];
    *(float4*)dst       = make_float4(acc[i][0], acc[i][1], acc[i][2], acc[i][3]);
    *(float4*)(dst + 4) = make_float4(acc[i][4], acc[i][5], acc[i][6], acc[i][7]);
  }

  #pragma unroll
  for (int i = 0; i < 8; i++) {
    float s = 0.0f;
    #pragma unroll
    for (int j = 0; j < 8; j++) s += acc[i][j];
    red[ty][i][tx] = s;
  }
  __syncthreads();
  if (tid < 128) {
    float s = 0.0f;
    #pragma unroll
    for (int t = 0; t < 16; t++) s += red[tid >> 3][tid & 7][t];
    d_psum[blockIdx.x * DoC + tid] = s;
  }
  __syncthreads();
  #pragma unroll
  for (int i = 0; i < 8; i++) {
    float s = 0.0f;
    #pragma unroll
    for (int j = 0; j < 8; j++) s += acc[i][j] * acc[i][j];
    red[ty][i][tx] = s;
  }
  __syncthreads();
  if (tid < 128) {
    float s = 0.0f;
    #pragma unroll
    for (int t = 0; t < 16; t++) s += red[tid >> 3][tid & 7][t];
    d_psq[blockIdx.x * DoC + tid] = s;
  }
}

// ---------------- out = relu(bn2(z2)) ----------------
__global__ __launch_bounds__(256) void final_kernel(float* __restrict__ out) {
  int e4 = blockIdx.x * 256 + threadIdx.x;   // float4 index, 1,048,576 total
  int ch = (e4 >> 12) & 127;
  float a = d_bn2[ch], d = d_bn2[DoC + ch];
  float4 v = *((const float4*)d_z2 + e4);
  v.x = fmaxf(fmaf(a, v.x, d), 0.0f);
  v.y = fmaxf(fmaf(a, v.y, d), 0.0f);
  v.z = fmaxf(fmaf(a, v.z, d), 0.0f);
  v.w = fmaxf(fmaf(a, v.w, d), 0.0f);
  *((float4*)out + e4) = v;
}

// ---------------- launch ----------------
extern "C" void kernel_launch(void* const* d_in, const int* in_sizes, int n_in,
                              void* d_out, int out_size) {
  const float* x       = (const float*)d_in[0];
  const float* xyz     = (const float*)d_in[1];
  const float* sub_x   = (const float*)d_in[2];
  const float* sub_xyz = (const float*)d_in[3];
  const float* W1      = (const float*)d_in[4];
  const float* g1      = (const float*)d_in[5];
  const float* b1      = (const float*)d_in[6];
  const float* W2      = (const float*)d_in[7];
  const float* g2      = (const float*)d_in[8];
  const float* b2      = (const float*)d_in[9];
  float* out = (float*)d_out;

  transpose_w_kernel<<<256, 256>>>(W1, W2);
  knn_kernel<<<128, 256>>>(xyz, sub_xyz);
  gemmP_kernel<<<64, 256>>>(sub_x);
  gemm1_kernel<<<256, 256>>>(x);
  bn_finalize_kernel<<<1, 128>>>(g1, b1, 0);
  gemm2_kernel<<<256, 256>>>();
  bn_finalize_kernel<<<1, 128>>>(g2, b2, 1);
  final_kernel<<<4096, 256>>>(out);
}

// round 2
// speedup vs baseline: 1.5879x; 1.5879x over previous
#include <cuda_runtime.h>

#define Bc   2
#define Mq   16384
#define Np   4096
#define Cin  128
#define CsF  256
#define DoC  128
#define K1   384
#define NCOLS (Bc*Mq)        // 32768
#define NBLK  256            // gemm1/gemm2 grid size
#define PH   2048            // points per half (knn split)

// ---------------- scratch (device globals; no runtime allocation) -------------
__device__ __align__(16) float d_W1t[K1*DoC];
__device__ __align__(16) float d_W2t[DoC*DoC];
__device__ __align__(16) float d_P  [Bc*Np*DoC];
__device__ float d_cd[Bc*Mq*6];
__device__ int   d_ci[Bc*Mq*6];
__device__ int   d_idx[Bc*Mq*3];
__device__ float d_w  [Bc*Mq*3];
__device__ __align__(16) float d_z1 [Bc*DoC*Mq];
__device__ __align__(16) float d_z2 [Bc*DoC*Mq];
__device__ float d_psum[NBLK*DoC];
__device__ float d_psq [NBLK*DoC];
__device__ float d_bn1[2*DoC];
__device__ float d_bn2[2*DoC];

// ---------------- cp.async helpers ----------------
__device__ __forceinline__ void cp16(float* s, const float* g) {
  unsigned sa = (unsigned)__cvta_generic_to_shared(s);
  asm volatile("cp.async.cg.shared.global [%0], [%1], 16;\n" :: "r"(sa), "l"(g));
}
__device__ __forceinline__ void cp_commit() { asm volatile("cp.async.commit_group;\n"); }
template<int N> __device__ __forceinline__ void cp_wait() {
  asm volatile("cp.async.wait_group %0;\n" :: "n"(N));
}

// ---------------- W transpose ----------------
__global__ __launch_bounds__(256) void transpose_w_kernel(
    const float* __restrict__ W1, const float* __restrict__ W2) {
  int e = blockIdx.x * 256 + threadIdx.x;
  if (e < K1*DoC) {
    int k = e >> 7, o = e & 127;
    d_W1t[e] = W1[o*K1 + k];
  } else {
    int e2 = e - K1*DoC;
    int k = e2 >> 7, o = e2 & 127;
    d_W2t[e2] = W2[o*DoC + k];
  }
}

// ---------------- 3-NN search: split point dim in 2, float4 smem ----------------
__global__ __launch_bounds__(256) void knn_kernel(
    const float* __restrict__ xyz, const float* __restrict__ sub_xyz) {
  __shared__ float4 pts[PH];   // 32KB
  int b    = blockIdx.x >> 7;
  int half = (blockIdx.x >> 6) & 1;
  int m    = ((blockIdx.x & 63) << 8) + threadIdx.x;
  const float* sp = sub_xyz + (size_t)b * 3 * Np + half * PH;
  for (int i = threadIdx.x; i < PH; i += 256) {
    float px = sp[i], py = sp[Np + i], pz = sp[2*Np + i];
    pts[i] = make_float4(px, py, pz, fmaf(px, px, fmaf(py, py, pz*pz)));
  }
  __syncthreads();
  const float* qp = xyz + (size_t)b * 3 * Mq;
  float nx = -2.0f * qp[m], ny = -2.0f * qp[Mq + m], nz = -2.0f * qp[2*Mq + m];

  // score e = |p|^2 - 2 q.p  (monotone in true distance for fixed q)
  float c0 = 3.4e38f, c1 = 3.4e38f, c2 = 3.4e38f;
  int j0 = 0, j1 = 0, j2 = 0;
  #pragma unroll 8
  for (int i = 0; i < PH; i++) {
    float4 p = pts[i];
    float e = fmaf(nx, p.x, fmaf(ny, p.y, fmaf(nz, p.z, p.w)));
    if (e < c2) {
      if (e < c1) {
        c2 = c1; j2 = j1;
        if (e < c0) { c1 = c0; j1 = j0; c0 = e; j0 = i; }
        else        { c1 = e; j1 = i; }
      } else { c2 = e; j2 = i; }
    }
  }
  size_t base = ((size_t)(b * Mq + m) * 2 + half) * 3;
  int off = half * PH;
  d_cd[base + 0] = c0; d_cd[base + 1] = c1; d_cd[base + 2] = c2;
  d_ci[base + 0] = j0 + off; d_ci[base + 1] = j1 + off; d_ci[base + 2] = j2 + off;
}

// ---------------- merge 6 candidates -> final idx/weights ----------------
__global__ __launch_bounds__(256) void knn_merge_kernel(const float* __restrict__ xyz) {
  int g = blockIdx.x * 256 + threadIdx.x;   // 0..32767
  int b = g >> 14, m = g & (Mq - 1);
  const float* qp = xyz + (size_t)b * 3 * Mq;
  float qx = qp[m], qy = qp[Mq + m], qz = qp[2*Mq + m];
  float qq = fmaf(qx, qx, fmaf(qy, qy, qz*qz));
  float c0 = 3.4e38f, c1 = 3.4e38f, c2 = 3.4e38f;
  int j0 = 0, j1 = 0, j2 = 0;
  size_t base = (size_t)g * 6;
  #pragma unroll
  for (int t = 0; t < 6; t++) {            // half0 first -> stable on ties
    float e = d_cd[base + t];
    int  id = d_ci[base + t];
    if (e < c2) {
      if (e < c1) {
        c2 = c1; j2 = j1;
        if (e < c0) { c1 = c0; j1 = j0; c0 = e; j0 = id; }
        else        { c1 = e; j1 = id; }
      } else { c2 = e; j2 = id; }
    }
  }
  float d0 = fmaxf(c0 + qq, 0.0f);
  float d1 = fmaxf(c1 + qq, 0.0f);
  float d2v = fmaxf(c2 + qq, 0.0f);
  float w0 = 1.0f / (d0 + 1e-8f);
  float w1 = 1.0f / (d1 + 1e-8f);
  float w2 = 1.0f / (d2v + 1e-8f);
  float inv = 1.0f / (w0 + w1 + w2);
  d_idx[g*3 + 0] = j0; d_idx[g*3 + 1] = j1; d_idx[g*3 + 2] = j2;
  d_w[g*3 + 0] = w0*inv; d_w[g*3 + 1] = w1*inv; d_w[g*3 + 2] = w2*inv;
}

// ---------------- P = W1[:,128:384] @ sub_x, stored [b][n][o]; 64-col tiles ----------------
__global__ __launch_bounds__(256) void gemmP_kernel(const float* __restrict__ sub_x) {
  extern __shared__ float smem[];
  float* Ws = smem;            // [2][32][128]
  float* Xs = smem + 8192;     // [2][32][64]
  int b  = blockIdx.x >> 6;
  int n0 = (blockIdx.x & 63) << 6;
  int tid = threadIdx.x;
  int tx = tid & 15, ty = tid >> 4;
  const float* xb = sub_x + (size_t)b * CsF * Np;
  float acc[8][4];
  #pragma unroll
  for (int i = 0; i < 8; i++)
    #pragma unroll
    for (int j = 0; j < 4; j++) acc[i][j] = 0.0f;

  auto load_chunk = [&](int kc, int s) {
    float* Wd = Ws + s * 4096;
    float* Xd = Xs + s * 2048;
    #pragma unroll
    for (int k = 0; k < 4; k++) {
      int e4 = tid + k*256, kk = e4 >> 5, c = (e4 & 31) << 2;
      cp16(Wd + kk*128 + c, d_W1t + (size_t)(Cin + kc + kk)*DoC + c);
    }
    #pragma unroll
    for (int k = 0; k < 2; k++) {
      int e4 = tid + k*256, kk = e4 >> 4, c = (e4 & 15) << 2;
      cp16(Xd + kk*64 + c, xb + (size_t)(kc + kk)*Np + n0 + c);
    }
  };
  load_chunk(0, 0); cp_commit();
  for (int ch = 0; ch < 8; ch++) {
    if (ch < 7) { load_chunk((ch+1)*32, (ch+1)&1); cp_commit(); cp_wait<1>(); }
    else        { cp_wait<0>(); }
    __syncthreads();
    const float* Wp = Ws + (ch & 1) * 4096;
    const float* Xp = Xs + (ch & 1) * 2048;
    #pragma unroll
    for (int kk = 0; kk < 32; kk++) {
      float a[8], bb[4];
      *(float4*)&a[0]  = *(const float4*)(Wp + kk*128 + ty*8);
      *(float4*)&a[4]  = *(const float4*)(Wp + kk*128 + ty*8 + 4);
      *(float4*)&bb[0] = *(const float4*)(Xp + kk*64 + tx*4);
      #pragma unroll
      for (int i = 0; i < 8; i++)
        #pragma unroll
        for (int j = 0; j < 4; j++) acc[i][j] = fmaf(a[i], bb[j], acc[i][j]);
    }
    __syncthreads();
  }
  #pragma unroll
  for (int j = 0; j < 4; j++) {
    float* dst = &d_P[(((size_t)b * Np) + n0 + tx*4 + j) * DoC + ty*8];
    *(float4*)dst       = make_float4(acc[0][j], acc[1][j], acc[2][j], acc[3][j]);
    *(float4*)(dst + 4) = make_float4(acc[4][j], acc[5][j], acc[6][j], acc[7][j]);
  }
}

// ---------------- z1 = W1a @ x + gather(P), + block stats ----------------
__global__ __launch_bounds__(256, 2) void gemm1_kernel(const float* __restrict__ x) {
  extern __shared__ float smem[];
  float* Ws   = smem;                    // [2][32][128]
  float* Xs   = smem + 8192;             // [2][32][128]
  int*   sidx = (int*)(smem + 16384);    // 384
  float* sw   = smem + 16768;            // 384
  float* red  = smem + 17152;            // [128][17]
  int n0g = blockIdx.x << 7;
  int b   = n0g >> 14;
  int m0  = n0g & (Mq - 1);
  int tid = threadIdx.x;
  int tx = tid & 15, ty = tid >> 4;
  const float* xb = x + (size_t)b * Cin * Mq;
  float acc[8][8];
  #pragma unroll
  for (int i = 0; i < 8; i++)
    #pragma unroll
    for (int j = 0; j < 8; j++) acc[i][j] = 0.0f;

  auto load_chunk = [&](int kc, int s) {
    float* Wd = Ws + s * 4096;
    float* Xd = Xs + s * 4096;
    #pragma unroll
    for (int k = 0; k < 4; k++) {
      int e4 = tid + k*256, kk = e4 >> 5, c = (e4 & 31) << 2;
      cp16(Wd + kk*128 + c, d_W1t + (size_t)(kc + kk)*DoC + c);
      cp16(Xd + kk*128 + c, xb + (size_t)(kc + kk)*Mq + m0 + c);
    }
  };
  load_chunk(0, 0); cp_commit();
  for (int ch = 0; ch < 4; ch++) {
    if (ch < 3) { load_chunk((ch+1)*32, (ch+1)&1); cp_commit(); cp_wait<1>(); }
    else        { cp_wait<0>(); }
    __syncthreads();
    const float* Wp = Ws + (ch & 1) * 4096;
    const float* Xp = Xs + (ch & 1) * 4096;
    #pragma unroll
    for (int kk = 0; kk < 32; kk++) {
      float a[8], bb[8];
      *(float4*)&a[0]  = *(const float4*)(Wp + kk*128 + ty*8);
      *(float4*)&a[4]  = *(const float4*)(Wp + kk*128 + ty*8 + 4);
      *(float4*)&bb[0] = *(const float4*)(Xp + kk*128 + tx*8);
      *(float4*)&bb[4] = *(const float4*)(Xp + kk*128 + tx*8 + 4);
      #pragma unroll
      for (int i = 0; i < 8; i++)
        #pragma unroll
        for (int j = 0; j < 8; j++) acc[i][j] = fmaf(a[i], bb[j], acc[i][j]);
    }
    __syncthreads();
  }

  // gather-interpolate through P
  {
    size_t cb = ((size_t)(b * Mq + m0)) * 3;
    for (int e = tid; e < 384; e += 256) { sidx[e] = d_idx[cb + e]; sw[e] = d_w[cb + e]; }
  }
  __syncthreads();
  #pragma unroll
  for (int j = 0; j < 8; j++) {
    int col = tx*8 + j;
    #pragma unroll
    for (int t = 0; t < 3; t++) {
      int   id = sidx[col*3 + t];
      float wt = sw  [col*3 + t];
      const float* pr = &d_P[(((size_t)b * Np) + id) * DoC + ty*8];
      float4 p0 = *(const float4*)pr;
      float4 p1 = *(const float4*)(pr + 4);
      acc[0][j] = fmaf(wt, p0.x, acc[0][j]);
      acc[1][j] = fmaf(wt, p0.y, acc[1][j]);
      acc[2][j] = fmaf(wt, p0.z, acc[2][j]);
      acc[3][j] = fmaf(wt, p0.w, acc[3][j]);
      acc[4][j] = fmaf(wt, p1.x, acc[4][j]);
      acc[5][j] = fmaf(wt, p1.y, acc[5][j]);
      acc[6][j] = fmaf(wt, p1.z, acc[6][j]);
      acc[7][j] = fmaf(wt, p1.w, acc[7][j]);
    }
  }

  // store z1
  #pragma unroll
  for (int i = 0; i < 8; i++) {
    float* dst = &d_z1[((size_t)(b * DoC + ty*8 + i)) * Mq + m0 + tx*8];
    *(float4*)dst       = make_float4(acc[i][0], acc[i][1], acc[i][2], acc[i][3]);
    *(float4*)(dst + 4) = make_float4(acc[i][4], acc[i][5], acc[i][6], acc[i][7]);
  }

  // deterministic per-block channel stats
  #pragma unroll
  for (int i = 0; i < 8; i++) {
    float s = 0.0f;
    #pragma unroll
    for (int j = 0; j < 8; j++) s += acc[i][j];
    red[(ty*8 + i)*17 + tx] = s;
  }
  __syncthreads();
  if (tid < 128) {
    float s = 0.0f;
    #pragma unroll
    for (int t = 0; t < 16; t++) s += red[tid*17 + t];
    d_psum[blockIdx.x * DoC + tid] = s;
  }
  __syncthreads();
  #pragma unroll
  for (int i = 0; i < 8; i++) {
    float s = 0.0f;
    #pragma unroll
    for (int j = 0; j < 8; j++) s += acc[i][j] * acc[i][j];
    red[(ty*8 + i)*17 + tx] = s;
  }
  __syncthreads();
  if (tid < 128) {
    float s = 0.0f;
    #pragma unroll
    for (int t = 0; t < 16; t++) s += red[tid*17 + t];
    d_psq[blockIdx.x * DoC + tid] = s;
  }
}

// ---------------- BN finalize ----------------
__global__ void bn_finalize_kernel(const float* __restrict__ g,
                                   const float* __restrict__ bias, int which) {
  __shared__ float ss[512], sq[512];
  int tid = threadIdx.x;               // 512
  int ch = tid & 127, part = tid >> 7;
  float s = 0.0f, q = 0.0f;
  for (int blk = part; blk < NBLK; blk += 4) {
    s += d_psum[blk * DoC + ch];
    q += d_psq [blk * DoC + ch];
  }
  ss[tid] = s; sq[tid] = q;
  __syncthreads();
  if (tid < 128) {
    float S = ss[tid] + ss[tid+128] + ss[tid+256] + ss[tid+384];
    float Q = sq[tid] + sq[tid+128] + sq[tid+256] + sq[tid+384];
    const float invN = 1.0f / (float)NCOLS;
    float mean = S * invN;
    float var  = Q * invN - mean * mean;
    float rstd = rsqrtf(var + 1e-5f);
    float a = g[tid] * rstd;
    float d = bias[tid] - mean * a;
    float* ab = which ? d_bn2 : d_bn1;
    ab[tid] = a; ab[DoC + tid] = d;
  }
}

// ---------------- z2 = W2 @ relu(bn1(z1)), + block stats ----------------
__global__ __launch_bounds__(256, 2) void gemm2_kernel() {
  extern __shared__ float smem[];
  float* Ws  = smem;             // [2][32][128]
  float* Xs  = smem + 8192;      // [2][32][128]
  float* sa  = smem + 16384;     // 128
  float* sd  = smem + 16512;     // 128
  float* red = smem + 16640;     // [128][17]
  int n0g = blockIdx.x << 7;
  int b   = n0g >> 14;
  int m0  = n0g & (Mq - 1);
  int tid = threadIdx.x;
  int tx = tid & 15, ty = tid >> 4;
  if (tid < 128) { sa[tid] = d_bn1[tid]; sd[tid] = d_bn1[DoC + tid]; }
  const float* zb = d_z1 + (size_t)b * DoC * Mq;
  float acc[8][8];
  #pragma unroll
  for (int i = 0; i < 8; i++)
    #pragma unroll
    for (int j = 0; j < 8; j++) acc[i][j] = 0.0f;

  auto load_chunk = [&](int kc, int s) {
    float* Wd = Ws + s * 4096;
    float* Xd = Xs + s * 4096;
    #pragma unroll
    for (int k = 0; k < 4; k++) {
      int e4 = tid + k*256, kk = e4 >> 5, c = (e4 & 31) << 2;
      cp16(Wd + kk*128 + c, d_W2t + (size_t)(kc + kk)*DoC + c);
      cp16(Xd + kk*128 + c, zb + (size_t)(kc + kk)*Mq + m0 + c);
    }
  };
  load_chunk(0, 0); cp_commit();
  for (int ch = 0; ch < 4; ch++) {
    if (ch < 3) { load_chunk((ch+1)*32, (ch+1)&1); cp_commit(); cp_wait<1>(); }
    else        { cp_wait<0>(); }
    __syncthreads();
    float* Xp = Xs + (ch & 1) * 4096;
    const float* Wp = Ws + (ch & 1) * 4096;
    int kc = ch * 32;
    // apply relu(bn1(.)) in place on this chunk
    #pragma unroll
    for (int k = 0; k < 4; k++) {
      int e4 = tid + k*256, kk = e4 >> 5, c = (e4 & 31) << 2;
      float A = sa[kc + kk], D = sd[kc + kk];
      float4 v = *(float4*)(Xp + kk*128 + c);
      v.x = fmaxf(fmaf(A, v.x, D), 0.0f);
      v.y = fmaxf(fmaf(A, v.y, D), 0.0f);
      v.z = fmaxf(fmaf(A, v.z, D), 0.0f);
      v.w = fmaxf(fmaf(A, v.w, D), 0.0f);
      *(float4*)(Xp + kk*128 + c) = v;
    }
    __syncthreads();
    #pragma unroll
    for (int kk = 0; kk < 32; kk++) {
      float a[8], bb[8];
      *(float4*)&a[0]  = *(const float4*)(Wp + kk*128 + ty*8);
      *(float4*)&a[4]  = *(const float4*)(Wp + kk*128 + ty*8 + 4);
      *(float4*)&bb[0] = *(const float4*)(Xp + kk*128 + tx*8);
      *(float4*)&bb[4] = *(const float4*)(Xp + kk*128 + tx*8 + 4);
      #pragma unroll
      for (int i = 0; i < 8; i++)
        #pragma unroll
        for (int j = 0; j < 8; j++) acc[i][j] = fmaf(a[i], bb[j], acc[i][j]);
    }
    __syncthreads();
  }

  #pragma unroll
  for (int i = 0; i < 8; i++) {
    float* dst = &d_z2[((size_t)(b * DoC + ty*8 + i)) * Mq + m0 + tx*8];
    *(float4*)dst       = make_float4(acc[i][0], acc[i][1], acc[i][2], acc[i][3]);
    *(float4*)(dst + 4) = make_float4(acc[i][4], acc[i][5], acc[i][6], acc[i][7]);
  }

  #pragma unroll
  for (int i = 0; i < 8; i++) {
    float s = 0.0f;
    #pragma unroll
    for (int j = 0; j < 8; j++) s += acc[i][j];
    red[(ty*8 + i)*17 + tx] = s;
  }
  __syncthreads();
  if (tid < 128) {
    float s = 0.0f;
    #pragma unroll
    for (int t = 0; t < 16; t++) s += red[tid*17 + t];
    d_psum[blockIdx.x * DoC + tid] = s;
  }
  __syncthreads();
  #pragma unroll
  for (int i = 0; i < 8; i++) {
    float s = 0.0f;
    #pragma unroll
    for (int j = 0; j < 8; j++) s += acc[i][j] * acc[i][j];
    red[(ty*8 + i)*17 + tx] = s;
  }
  __syncthreads();
  if (tid < 128) {
    float s = 0.0f;
    #pragma unroll
    for (int t = 0; t < 16; t++) s += red[tid*17 + t];
    d_psq[blockIdx.x * DoC + tid] = s;
  }
}

// ---------------- out = relu(bn2(z2)) ----------------
__global__ __launch_bounds__(256) void final_kernel(float* __restrict__ out) {
  int e4 = blockIdx.x * 256 + threadIdx.x;
  int ch = (e4 >> 12) & 127;
  float a = d_bn2[ch], d = d_bn2[DoC + ch];
  float4 v = *((const float4*)d_z2 + e4);
  v.x = fmaxf(fmaf(a, v.x, d), 0.0f);
  v.y = fmaxf(fmaf(a, v.y, d), 0.0f);
  v.z = fmaxf(fmaf(a, v.z, d), 0.0f);
  v.w = fmaxf(fmaf(a, v.w, d), 0.0f);
  *((float4*)out + e4) = v;
}

// ---------------- launch ----------------
extern "C" void kernel_launch(void* const* d_in, const int* in_sizes, int n_in,
                              void* d_out, int out_size) {
  const float* x       = (const float*)d_in[0];
  const float* xyz     = (const float*)d_in[1];
  const float* sub_x   = (const float*)d_in[2];
  const float* sub_xyz = (const float*)d_in[3];
  const float* W1      = (const float*)d_in[4];
  const float* g1      = (const float*)d_in[5];
  const float* b1      = (const float*)d_in[6];
  const float* W2      = (const float*)d_in[7];
  const float* g2      = (const float*)d_in[8];
  const float* b2      = (const float*)d_in[9];
  float* out = (float*)d_out;

  cudaFuncSetAttribute(gemmP_kernel, cudaFuncAttributeMaxDynamicSharedMemorySize, 49152);
  cudaFuncSetAttribute(gemm1_kernel, cudaFuncAttributeMaxDynamicSharedMemorySize, 77312);
  cudaFuncSetAttribute(gemm2_kernel, cudaFuncAttributeMaxDynamicSharedMemorySize, 75264);

  transpose_w_kernel<<<256, 256>>>(W1, W2);
  knn_kernel<<<256, 256>>>(xyz, sub_xyz);
  knn_merge_kernel<<<128, 256>>>(xyz);
  gemmP_kernel<<<128, 256, 49152>>>(sub_x);
  gemm1_kernel<<<256, 256, 77312>>>(x);
  bn_finalize_kernel<<<1, 512>>>(g1, b1, 0);
  gemm2_kernel<<<256, 256, 75264>>>();
  bn_finalize_kernel<<<1, 512>>>(g2, b2, 1);
  final_kernel<<<4096, 256>>>(out);
}